// round 4
// baseline (speedup 1.0000x reference)
#include <cuda_runtime.h>
#include <math.h>
#include <stdint.h>

#define Bq 16
#define Nq 512
#define Dq 768
#define Hq 12
#define DKq 64
#define TOK (Bq*Nq)   // 8192

// Scratch
__device__ float g_x[TOK*Dq];
__device__ float g_q[TOK*Dq];
__device__ float g_k[TOK*Dq];
__device__ float g_v[TOK*Dq];
__device__ float g_o[TOK*Dq];
__device__ float g_px[TOK];
__device__ float g_py[TOK];
__device__ int   g_btab[201];

// ---------------------------------------------------------------------------
// helpers
// ---------------------------------------------------------------------------
__device__ __forceinline__ uint32_t f2tf32(float f) {
    uint32_t u;
    asm("cvt.rna.tf32.f32 %0, %1;" : "=r"(u) : "f"(f));
    return u;
}
__device__ __forceinline__ void mma_tf32(float c[4], const uint32_t a[4], const uint32_t b[2]) {
    asm volatile(
        "mma.sync.aligned.m16n8k8.row.col.f32.tf32.tf32.f32 "
        "{%0,%1,%2,%3}, {%4,%5,%6,%7}, {%8,%9}, {%0,%1,%2,%3};"
        : "+f"(c[0]), "+f"(c[1]), "+f"(c[2]), "+f"(c[3])
        : "r"(a[0]), "r"(a[1]), "r"(a[2]), "r"(a[3]), "r"(b[0]), "r"(b[1]));
}

// ---------------------------------------------------------------------------
// tf32 mma.sync GEMM: C[8192,768] = A[8192,768] @ W[768,768]^T + bias
// CTA tile 128x128, KC=32. 8 warps in 4(m) x 2(n); warp tile 32x64.
// ---------------------------------------------------------------------------
#define KC 32
#define LDT 40   // smem row stride (floats), padded

__global__ void __launch_bounds__(256) hmma_gemm(const float* __restrict__ A,
                                                 const float* __restrict__ W,
                                                 const float* __restrict__ bias,
                                                 float* __restrict__ C) {
    __shared__ uint32_t As[128 * LDT];
    __shared__ uint32_t Ws[128 * LDT];
    int tid = threadIdx.x;
    int wid = tid >> 5, lane = tid & 31;
    int wm = (wid >> 1) * 32;          // warp m offset in tile
    int wn = (wid & 1) * 64;           // warp n offset
    int gid = lane >> 2;               // 0..7
    int lig = lane & 3;                // 0..3
    int m0 = blockIdx.y * 128, n0 = blockIdx.x * 128;

    const float* Ap = A + (size_t)m0 * Dq;
    const float* Wp = W + (size_t)n0 * Dq;

    float acc[2][8][4];
    #pragma unroll
    for (int mi = 0; mi < 2; mi++)
        #pragma unroll
        for (int ni = 0; ni < 8; ni++)
            #pragma unroll
            for (int j = 0; j < 4; j++) acc[mi][ni][j] = 0.f;

    for (int k0 = 0; k0 < Dq; k0 += KC) {
        #pragma unroll
        for (int i = 0; i < 4; i++) {
            int idx = tid + i * 256;
            int r = idx >> 3, c = (idx & 7) * 4;
            float4 av = *(const float4*)(Ap + (size_t)r * Dq + k0 + c);
            float4 wv = *(const float4*)(Wp + (size_t)r * Dq + k0 + c);
            uint32_t* as = &As[r * LDT + c];
            uint32_t* ws = &Ws[r * LDT + c];
            as[0] = f2tf32(av.x); as[1] = f2tf32(av.y); as[2] = f2tf32(av.z); as[3] = f2tf32(av.w);
            ws[0] = f2tf32(wv.x); ws[1] = f2tf32(wv.y); ws[2] = f2tf32(wv.z); ws[3] = f2tf32(wv.w);
        }
        __syncthreads();
        #pragma unroll
        for (int ks = 0; ks < KC / 8; ks++) {
            int k8 = ks * 8;
            uint32_t afr[2][4];
            #pragma unroll
            for (int mi = 0; mi < 2; mi++) {
                int rb = wm + mi * 16;
                afr[mi][0] = As[(rb + gid) * LDT + k8 + lig];
                afr[mi][1] = As[(rb + 8 + gid) * LDT + k8 + lig];
                afr[mi][2] = As[(rb + gid) * LDT + k8 + 4 + lig];
                afr[mi][3] = As[(rb + 8 + gid) * LDT + k8 + 4 + lig];
            }
            #pragma unroll
            for (int ni = 0; ni < 8; ni++) {
                uint32_t bfr[2];
                int nb = wn + ni * 8;
                bfr[0] = Ws[(nb + gid) * LDT + k8 + lig];
                bfr[1] = Ws[(nb + gid) * LDT + k8 + 4 + lig];
                mma_tf32(acc[0][ni], afr[0], bfr);
                mma_tf32(acc[1][ni], afr[1], bfr);
            }
        }
        __syncthreads();
    }

    // Epilogue: c0,c1 at (row=gid, col=2*lig, 2*lig+1); c2,c3 at row=gid+8
    #pragma unroll
    for (int mi = 0; mi < 2; mi++) {
        int rbase = m0 + wm + mi * 16 + gid;
        #pragma unroll
        for (int ni = 0; ni < 8; ni++) {
            int col = n0 + wn + ni * 8 + 2 * lig;
            float b0 = bias[col], b1 = bias[col + 1];
            float* p0 = C + (size_t)rbase * Dq + col;
            float* p1 = C + (size_t)(rbase + 8) * Dq + col;
            float2 o0 = {acc[mi][ni][0] + b0, acc[mi][ni][1] + b1};
            float2 o1 = {acc[mi][ni][2] + b0, acc[mi][ni][3] + b1};
            *(float2*)p0 = o0;
            *(float2*)p1 = o1;
        }
    }
}

// ---------------------------------------------------------------------------
// LayerNorm
// ---------------------------------------------------------------------------
__global__ void __launch_bounds__(256) ln_kernel(const float* __restrict__ f,
                                                 const float* __restrict__ gamma,
                                                 const float* __restrict__ beta) {
    int t = blockIdx.x;
    const float* in = f + (size_t)t * Dq;
    float* out = g_x + (size_t)t * Dq;
    int tid = threadIdx.x;
    float v0 = in[tid], v1 = in[tid + 256], v2 = in[tid + 512];

    __shared__ float red[8];
    __shared__ float bc;

    float s = v0 + v1 + v2;
    #pragma unroll
    for (int o = 16; o > 0; o >>= 1) s += __shfl_down_sync(0xffffffffu, s, o);
    if ((tid & 31) == 0) red[tid >> 5] = s;
    __syncthreads();
    if (tid == 0) {
        float tot = 0.f;
        #pragma unroll
        for (int i = 0; i < 8; i++) tot += red[i];
        bc = tot * (1.0f / 768.0f);
    }
    __syncthreads();
    float mean = bc;
    float d0 = v0 - mean, d1 = v1 - mean, d2 = v2 - mean;
    float ss = d0 * d0 + d1 * d1 + d2 * d2;
    #pragma unroll
    for (int o = 16; o > 0; o >>= 1) ss += __shfl_down_sync(0xffffffffu, ss, o);
    __syncthreads();
    if ((tid & 31) == 0) red[tid >> 5] = ss;
    __syncthreads();
    if (tid == 0) {
        float tot = 0.f;
        #pragma unroll
        for (int i = 0; i < 8; i++) tot += red[i];
        bc = tot * (1.0f / 768.0f);
    }
    __syncthreads();
    float inv = rsqrtf(bc + 1e-5f);
    out[tid]       = d0 * inv * gamma[tid]       + beta[tid];
    out[tid + 256] = d1 * inv * gamma[tid + 256] + beta[tid + 256];
    out[tid + 512] = d2 * inv * gamma[tid + 512] + beta[tid + 512];
}

// ---------------------------------------------------------------------------
// Patch bins
// ---------------------------------------------------------------------------
__global__ void __launch_bounds__(256) bins_kernel(const float* __restrict__ boxes,
                                                   const int* __restrict__ im) {
    int idx = blockIdx.x * blockDim.x + threadIdx.x;
    if (idx < 201) g_btab[idx] = (int)(2.0 * sqrt((double)idx));
    if (idx >= TOK) return;
    int b = idx / Nq;
    float wf = (float)im[b * 4 + 0];
    float hf = (float)im[b * 4 + 1];
    const float* bx = boxes + (size_t)idx * 4;
    float x1 = bx[0] * wf, y1 = bx[1] * hf, x2 = bx[2] * wf, y2 = bx[3] * hf;
    float spw = floorf(wf / 11.0f), sph = floorf(hf / 11.0f);
    float cx = floorf((x1 + x2) / 2.0f), cy = floorf((y1 + y2) / 2.0f);
    int px = 0, py = 0;
    #pragma unroll
    for (int i = 0; i < 11; i++) {
        float lo = (float)i * spw, hi = (float)(i + 1) * spw;
        if (lo <= cx && cx <= hi) { px = i; break; }
    }
    #pragma unroll
    for (int i = 0; i < 11; i++) {
        float lo = (float)i * sph, hi = (float)(i + 1) * sph;
        if (lo <= cy && cy <= hi) { py = i; break; }
    }
    g_px[idx] = (float)px;
    g_py[idx] = (float)py;
}

// ---------------------------------------------------------------------------
// Scores
// ---------------------------------------------------------------------------
__global__ void __launch_bounds__(256) scores_kernel(const float* __restrict__ dist_emb,
                                                     float* __restrict__ att) {
    int bh = blockIdx.z;
    int b = bh / Hq, h = bh - b * Hq;
    int q0 = blockIdx.y * 64, k0 = blockIdx.x * 64;
    __shared__ float Qs[64][65];
    __shared__ float Ks[64][65];
    __shared__ float biastab[201];
    __shared__ float pxq[64], pyq[64], pxk[64], pyk[64];
    int tid = threadIdx.x;

    for (int i = tid; i < 64 * 16; i += 256) {
        int r = i >> 4, c = (i & 15) * 4;
        float4 qv = *(const float4*)(g_q + ((size_t)((b * Nq + q0 + r) * Hq + h)) * DKq + c);
        Qs[r][c] = qv.x; Qs[r][c + 1] = qv.y; Qs[r][c + 2] = qv.z; Qs[r][c + 3] = qv.w;
        float4 kv = *(const float4*)(g_k + ((size_t)((b * Nq + k0 + r) * Hq + h)) * DKq + c);
        Ks[r][c] = kv.x; Ks[r][c + 1] = kv.y; Ks[r][c + 2] = kv.z; Ks[r][c + 3] = kv.w;
    }
    for (int i = tid; i < 201; i += 256)
        biastab[i] = dist_emb[g_btab[i] * Hq + h];
    if (tid < 64) {
        pxq[tid] = g_px[b * Nq + q0 + tid]; pyq[tid] = g_py[b * Nq + q0 + tid];
        pxk[tid] = g_px[b * Nq + k0 + tid]; pyk[tid] = g_py[b * Nq + k0 + tid];
    }
    __syncthreads();

    int ty = tid >> 4, tx = tid & 15;
    float acc[4][4] = {};
    #pragma unroll 8
    for (int kk = 0; kk < 64; kk++) {
        float a[4], bb[4];
        #pragma unroll
        for (int i = 0; i < 4; i++) a[i] = Qs[ty * 4 + i][kk];
        #pragma unroll
        for (int j = 0; j < 4; j++) bb[j] = Ks[tx * 4 + j][kk];
        #pragma unroll
        for (int i = 0; i < 4; i++)
            #pragma unroll
            for (int j = 0; j < 4; j++)
                acc[i][j] = fmaf(a[i], bb[j], acc[i][j]);
    }
    #pragma unroll
    for (int i = 0; i < 4; i++) {
        int q = q0 + ty * 4 + i;
        float pxi = pxq[ty * 4 + i], pyi = pyq[ty * 4 + i];
        #pragma unroll
        for (int j = 0; j < 4; j++) {
            int k = k0 + tx * 4 + j;
            float dx = pxk[tx * 4 + j] - pxi;
            float dy = pyk[tx * 4 + j] - pyi;
            int d2 = (int)(dx * dx + dy * dy);
            att[(((size_t)bh) * Nq + q) * Nq + k] = acc[i][j] * 0.125f + biastab[d2];
        }
    }
}

// ---------------------------------------------------------------------------
// Softmax
// ---------------------------------------------------------------------------
__global__ void __launch_bounds__(256) softmax_kernel(float* __restrict__ att) {
    size_t row = blockIdx.x;
    float* p = att + row * Nq;
    int tid = threadIdx.x;
    float a = p[tid], b2 = p[tid + 256];
    __shared__ float red[8];
    __shared__ float bc;

    float m = fmaxf(a, b2);
    #pragma unroll
    for (int o = 16; o > 0; o >>= 1) m = fmaxf(m, __shfl_down_sync(0xffffffffu, m, o));
    if ((tid & 31) == 0) red[tid >> 5] = m;
    __syncthreads();
    if (tid == 0) {
        float mm = red[0];
        #pragma unroll
        for (int i = 1; i < 8; i++) mm = fmaxf(mm, red[i]);
        bc = mm;
    }
    __syncthreads();
    float mx = bc;
    float e1 = expf(a - mx), e2 = expf(b2 - mx);
    float s = e1 + e2;
    #pragma unroll
    for (int o = 16; o > 0; o >>= 1) s += __shfl_down_sync(0xffffffffu, s, o);
    __syncthreads();
    if ((tid & 31) == 0) red[tid >> 5] = s;
    __syncthreads();
    if (tid == 0) {
        float ss = 0.f;
        #pragma unroll
        for (int i = 0; i < 8; i++) ss += red[i];
        bc = ss;
    }
    __syncthreads();
    float inv = 1.0f / bc;
    p[tid] = e1 * inv;
    p[tid + 256] = e2 * inv;
}

// ---------------------------------------------------------------------------
// AV
// ---------------------------------------------------------------------------
__global__ void __launch_bounds__(256) av_kernel(const float* __restrict__ att) {
    int bh = blockIdx.y;
    int b = bh / Hq, h = bh - b * Hq;
    int q0 = blockIdx.x * 64;
    __shared__ float As[64][33];
    __shared__ float Vs[32][65];
    int tid = threadIdx.x;
    int ty = tid >> 4, tx = tid & 15;
    float acc[4][4] = {};

    for (int kb = 0; kb < Nq; kb += 32) {
        for (int i = tid; i < 64 * 8; i += 256) {
            int r = i >> 3, c = (i & 7) * 4;
            float4 v = *(const float4*)(att + (((size_t)bh) * Nq + q0 + r) * Nq + kb + c);
            As[r][c] = v.x; As[r][c + 1] = v.y; As[r][c + 2] = v.z; As[r][c + 3] = v.w;
        }
        for (int i = tid; i < 32 * 16; i += 256) {
            int r = i >> 4, c = (i & 15) * 4;
            float4 v = *(const float4*)(g_v + ((size_t)((b * Nq + kb + r) * Hq + h)) * DKq + c);
            Vs[r][c] = v.x; Vs[r][c + 1] = v.y; Vs[r][c + 2] = v.z; Vs[r][c + 3] = v.w;
        }
        __syncthreads();
        #pragma unroll 8
        for (int kk = 0; kk < 32; kk++) {
            float a[4], bb[4];
            #pragma unroll
            for (int i = 0; i < 4; i++) a[i] = As[ty * 4 + i][kk];
            #pragma unroll
            for (int j = 0; j < 4; j++) bb[j] = Vs[kk][tx * 4 + j];
            #pragma unroll
            for (int i = 0; i < 4; i++)
                #pragma unroll
                for (int j = 0; j < 4; j++)
                    acc[i][j] = fmaf(a[i], bb[j], acc[i][j]);
        }
        __syncthreads();
    }
    #pragma unroll
    for (int i = 0; i < 4; i++) {
        int q = q0 + ty * 4 + i;
        #pragma unroll
        for (int j = 0; j < 4; j++)
            g_o[((size_t)((b * Nq + q) * Hq + h)) * DKq + tx * 4 + j] = acc[i][j];
    }
}

// ---------------------------------------------------------------------------
extern "C" void kernel_launch(void* const* d_in, const int* in_sizes, int n_in,
                              void* d_out, int out_size) {
    const float* features = (const float*)d_in[0];
    const float* boxes    = (const float*)d_in[1];
    const int*   im       = (const int*)d_in[2];
    const float* Wq = (const float*)d_in[3];  const float* bqv = (const float*)d_in[4];
    const float* Wk = (const float*)d_in[5];  const float* bkv = (const float*)d_in[6];
    const float* Wv = (const float*)d_in[7];  const float* bvv = (const float*)d_in[8];
    const float* Wo = (const float*)d_in[9];  const float* bov = (const float*)d_in[10];
    const float* gamma = (const float*)d_in[11];
    const float* beta  = (const float*)d_in[12];
    const float* demb  = (const float*)d_in[13];

    float* out = (float*)d_out;
    float* att = out + (size_t)TOK * Dq;

    void *px_, *pq_, *pk_, *pv_, *po_;
    cudaGetSymbolAddress(&px_, g_x);
    cudaGetSymbolAddress(&pq_, g_q);
    cudaGetSymbolAddress(&pk_, g_k);
    cudaGetSymbolAddress(&pv_, g_v);
    cudaGetSymbolAddress(&po_, g_o);

    ln_kernel<<<TOK, 256>>>(features, gamma, beta);
    bins_kernel<<<(TOK + 255) / 256, 256>>>(boxes, im);

    dim3 gproj(Dq / 128, TOK / 128);   // (6, 64)
    hmma_gemm<<<gproj, 256>>>((const float*)px_, Wq, bqv, (float*)pq_);
    hmma_gemm<<<gproj, 256>>>((const float*)px_, Wk, bkv, (float*)pk_);
    hmma_gemm<<<gproj, 256>>>((const float*)px_, Wv, bvv, (float*)pv_);

    scores_kernel<<<dim3(8, 8, Bq * Hq), 256>>>(demb, att);
    softmax_kernel<<<Bq * Hq * Nq, 256>>>(att);
    av_kernel<<<dim3(8, Bq * Hq), 256>>>(att);

    hmma_gemm<<<gproj, 256>>>((const float*)po_, Wo, bov, out);
}